// round 12
// baseline (speedup 1.0000x reference)
#include <cuda_runtime.h>
#include <cuda_bf16.h>
#include <math.h>

// ---------------- problem constants (fixed by the dataset) ----------------
#define NODES   10000
#define EDGES   20000
#define BGRAPHS 500
#define HDIM    64
#define NODE_D  11
#define EDGE_D  5
#define LAYERS  3
#define STEPS   3
#define BN_EPS  1e-5f
#define KSPLITS 4

// ---------------- scratch (static device globals; no allocation) ----------
__device__ float g_h[NODES * HDIM];       // node features
__device__ float g_tmp[NODES * HDIM];     // pre-BN features
__device__ float g_agg[NODES * HDIM];     // message aggregation
__device__ float g_e1T[HDIM * EDGES];     // edge MLP hidden, transposed [k][e]
__device__ float g_deg[NODES];
__device__ float g_bnsum[HDIM];
__device__ float g_bnsumsq[HDIM];
__device__ float g_hl[BGRAPHS * HDIM];
__device__ float g_cl[BGRAPHS * HDIM];
__device__ float g_r [BGRAPHS * HDIM];
__device__ float g_e [NODES];
__device__ float g_ex[NODES];
__device__ int   g_mkey[BGRAPHS];
__device__ float g_sden[BGRAPHS];

// monotone int key for float atomicMax
__device__ __forceinline__ int   fkey (float f) { int i = __float_as_int(f); return i >= 0 ? i : (i ^ 0x7fffffff); }
__device__ __forceinline__ float funkey(int i)  { return __int_as_float(i >= 0 ? i : (i ^ 0x7fffffff)); }
__device__ __forceinline__ float sigf(float x)  { return 1.f / (1.f + expf(-x)); }

// ---------------- packed f32x2 helpers (Blackwell FFMA2 path) -------------
__device__ __forceinline__ void ffma2(unsigned long long& d,
                                      unsigned long long a,
                                      unsigned long long b) {
    asm("fma.rn.f32x2 %0, %1, %2, %0;" : "+l"(d) : "l"(a), "l"(b));
}
__device__ __forceinline__ unsigned long long pack2(float lo, float hi) {
    unsigned long long r;
    asm("mov.b64 %0, {%1, %2};" : "=l"(r) : "f"(lo), "f"(hi));
    return r;
}
__device__ __forceinline__ float2 unpack2(unsigned long long v) {
    float2 f;
    asm("mov.b64 {%0, %1}, %2;" : "=f"(f.x), "=f"(f.y) : "l"(v));
    return f;
}

// ---------------- encoder: h = relu(x @ W_enc + b_enc); deg = 0 -----------
__global__ void k_encoder(const float* __restrict__ x,
                          const float* __restrict__ W_enc,
                          const float* __restrict__ b_enc) {
    int n = blockIdx.x;
    int j = threadIdx.x;                 // 64
    __shared__ float xr[NODE_D];
    if (j < NODE_D) xr[j] = x[n * NODE_D + j];
    if (j == 0)     g_deg[n] = 0.f;
    __syncthreads();
    float s = b_enc[j];
#pragma unroll
    for (int d = 0; d < NODE_D; d++) s = fmaf(xr[d], W_enc[d * HDIM + j], s);
    g_h[n * HDIM + j] = fmaxf(s, 0.f);
}

// ---------------- in-degree count ----------------------------------------
__global__ void k_degcount(const int* __restrict__ dst) {
    int e = blockIdx.x * 256 + threadIdx.x;
    if (e < EDGES) atomicAdd(&g_deg[dst[e]], 1.f);
}

// ---------------- edge MLP: e1T[k][e] = relu(ea @ eW1 + eb1) --------------
__global__ void __launch_bounds__(256) k_edge_mlp(const float* __restrict__ ea,
                                                  const float* __restrict__ W1l,
                                                  const float* __restrict__ b1l) {
    __shared__ float sa[64 * EDGE_D];    // 320 floats
    __shared__ float w1[EDGE_D * HDIM];  // 320 floats
    __shared__ float b1[HDIM];
    int tid = threadIdx.x;
    int eBase = blockIdx.x * 64;
    // grid-stride fills: 320 > blockDim (256) — must loop!
    for (int i = tid; i < 64 * EDGE_D; i += 256) {
        int gidx = eBase * EDGE_D + i;
        sa[i] = (gidx < EDGES * EDGE_D) ? ea[gidx] : 0.f;
    }
    for (int i = tid; i < EDGE_D * HDIM; i += 256) {
        w1[i] = W1l[i];
    }
    if (tid < HDIM) b1[tid] = b1l[tid];
    __syncthreads();
    for (int i = tid; i < 64 * HDIM; i += 256) {
        int e = i & 63, j = i >> 6;
        int ge = eBase + e;
        if (ge < EDGES) {
            float s = b1[j];
#pragma unroll
            for (int d = 0; d < EDGE_D; d++) s = fmaf(sa[e * EDGE_D + d], w1[d * HDIM + j], s);
            g_e1T[j * EDGES + ge] = fmaxf(s, 0.f);
        }
    }
}

// ---------------- zero agg + BN accumulators ------------------------------
__global__ void k_zero() {
    int idx = blockIdx.x * 256 + threadIdx.x;
    if (idx < NODES * HDIM) g_agg[idx] = 0.f;
    if (idx < HDIM) { g_bnsum[idx] = 0.f; g_bnsumsq[idx] = 0.f; }
}

// ---------------- big fused message GEMM (packed f32x2 / FFMA2) -----------
// msg[e,o] = sum_{k,h} e1[e,k] * h_src[e,h] * eW2[k*64+h, o]  (+ eb2 chunk)
// CTA: 64 edges x 64 outputs, 128 threads, split-K = 4.
// Microtile: 8 edges (as 4 f32x2 pairs) x 4 outputs, FFMA2 inner loop.
__global__ void __launch_bounds__(128, 4) k_msg(const float* __restrict__ eW2l,
                                                const float* __restrict__ eb2l,
                                                const int*   __restrict__ src,
                                                const int*   __restrict__ dst) {
    __shared__ float hsT[64][68];        // [h][edge], padded (16B-aligned rows)
    __shared__ float Bs[64 * 64];        // eW2 chunk [h][o]
    __shared__ float scale_s[64];        // e1[:,k] for this edge tile
    __shared__ int   dst_s[64];

    const int tid    = threadIdx.x;
    const int eBase  = blockIdx.x * 64;
    const int kSplit = blockIdx.y;       // 0..3

    // gather h_src tile, transpose into SMEM
    for (int i = tid; i < 64 * 64; i += 128) {
        int e = i >> 6, hh = i & 63;
        int ge = eBase + e;
        hsT[hh][e] = (ge < EDGES) ? g_h[src[ge] * HDIM + hh] : 0.f;
    }
    if (tid < 64) {
        int ge = eBase + tid;
        dst_s[tid] = (ge < EDGES) ? dst[ge] : -1;
    }

    // acc2[rp][c]: edge pair (r0+2rp, r0+2rp+1), output o0+c
    unsigned long long acc2[4][4];
#pragma unroll
    for (int rp = 0; rp < 4; rp++)
#pragma unroll
        for (int c = 0; c < 4; c++) acc2[rp][c] = 0ull;

    const int cg = tid & 15;             // column group
    const int rg = tid >> 4;             // row group
    const int o0 = cg * 4;
    const int r0 = rg * 8;

    const int kBeg = kSplit * 16;
    const int kEnd = (kSplit == KSPLITS - 1) ? 65 : (kBeg + 16);
    // k==64 is the eb2 bias pseudo-chunk (scale 1), carried by the last split

    for (int k = kBeg; k < kEnd; ++k) {
        __syncthreads();
        const float4* Bsrc = (const float4*)((k < 64) ? (eW2l + k * 4096) : eb2l);
#pragma unroll
        for (int i = 0; i < 8; ++i)
            ((float4*)Bs)[tid + i * 128] = Bsrc[tid + i * 128];
        if (tid < 64) {
            int ge = eBase + tid;
            scale_s[tid] = (k == 64) ? 1.f
                         : ((ge < EDGES) ? g_e1T[k * EDGES + ge] : 0.f);
        }
        __syncthreads();

        unsigned long long inner[4][4];
#pragma unroll
        for (int rp = 0; rp < 4; rp++)
#pragma unroll
            for (int c = 0; c < 4; c++) inner[rp][c] = 0ull;

#pragma unroll 8
        for (int hh = 0; hh < 64; ++hh) {
            // a pairs: consecutive edges, pre-packed by SMEM layout
            ulonglong2 a0 = *(const ulonglong2*)&hsT[hh][r0];      // (r0,r0+1),(r0+2,r0+3)
            ulonglong2 a1 = *(const ulonglong2*)&hsT[hh][r0 + 4];  // (r0+4..r0+7)
            float4 b4 = *(const float4*)&Bs[hh * 64 + o0];
            unsigned long long ap[4] = {a0.x, a0.y, a1.x, a1.y};
            unsigned long long bb[4] = {pack2(b4.x, b4.x), pack2(b4.y, b4.y),
                                        pack2(b4.z, b4.z), pack2(b4.w, b4.w)};
#pragma unroll
            for (int rp = 0; rp < 4; rp++)
#pragma unroll
                for (int c = 0; c < 4; c++)
                    ffma2(inner[rp][c], ap[rp], bb[c]);
        }
        // apply per-edge e1 scale for this k (pairs contiguous in scale_s)
#pragma unroll
        for (int rp = 0; rp < 4; rp++) {
            unsigned long long sp = *(const unsigned long long*)&scale_s[r0 + 2 * rp];
#pragma unroll
            for (int c = 0; c < 4; c++)
                ffma2(acc2[rp][c], sp, inner[rp][c]);
        }
    }

#pragma unroll
    for (int rp = 0; rp < 4; rp++) {
        int dA = dst_s[r0 + 2 * rp];
        int dB = dst_s[r0 + 2 * rp + 1];
#pragma unroll
        for (int c = 0; c < 4; c++) {
            float2 v = unpack2(acc2[rp][c]);
            if (dA >= 0) atomicAdd(&g_agg[dA * HDIM + o0 + c], v.x);
            if (dB >= 0) atomicAdd(&g_agg[dB * HDIM + o0 + c], v.y);
        }
    }
}

// ---------------- update: tmp = agg/deg + h@root + cbias, BN partials -----
__global__ void __launch_bounds__(256) k_update(const float* __restrict__ rootl,
                                                const float* __restrict__ cbiasl) {
    __shared__ float rs[64 * 64];
    __shared__ float hrow[16 * 64];
    __shared__ float red1[256];
    __shared__ float red2[256];
    int tid = threadIdx.x;
    int nBase = blockIdx.x * 16;
    for (int i = tid; i < 1024; i += 256) ((float4*)rs)[i] = ((const float4*)rootl)[i];
    for (int i = tid; i < 16 * 64; i += 256) {
        int ni = i >> 6, hh = i & 63;
        int n = nBase + ni;
        hrow[i] = (n < NODES) ? g_h[n * HDIM + hh] : 0.f;
    }
    __syncthreads();
    int o = tid & 63, nl = tid >> 6;
    float cb = cbiasl[o];
    float s1 = 0.f, s2 = 0.f;
    for (int ni = nl; ni < 16; ni += 4) {
        int n = nBase + ni;
        if (n < NODES) {
            float rdeg = 1.f / fmaxf(g_deg[n], 1.f);
            float v = fmaf(g_agg[n * HDIM + o], rdeg, cb);
#pragma unroll 16
            for (int hh = 0; hh < 64; hh++)
                v = fmaf(hrow[ni * 64 + hh], rs[hh * 64 + o], v);
            g_tmp[n * HDIM + o] = v;
            s1 += v;
            s2 = fmaf(v, v, s2);
        }
    }
    red1[tid] = s1; red2[tid] = s2;
    __syncthreads();
    if (tid < 64) {
        float a1 = red1[tid] + red1[tid + 64] + red1[tid + 128] + red1[tid + 192];
        float a2 = red2[tid] + red2[tid + 64] + red2[tid + 128] + red2[tid + 192];
        atomicAdd(&g_bnsum[tid], a1);
        atomicAdd(&g_bnsumsq[tid], a2);
    }
}

// ---------------- BN apply + relu + residual ------------------------------
__global__ void k_bn_apply(const float* __restrict__ gammal,
                           const float* __restrict__ betal) {
    int idx = blockIdx.x * 256 + threadIdx.x;
    if (idx >= NODES * HDIM) return;
    int o = idx & 63;
    const float invN = 1.f / (float)NODES;
    float mu  = g_bnsum[o] * invN;
    float var = g_bnsumsq[o] * invN - mu * mu;
    float inv = rsqrtf(var + BN_EPS);
    float v = (g_tmp[idx] - mu) * inv * gammal[o] + betal[o];
    g_h[idx] = fmaxf(v, 0.f) + g_h[idx];
}

// ---------------- Set2Set ----------------------------------------------
__global__ void k_s2s_init() {
    int idx = blockIdx.x * 256 + threadIdx.x;
    if (idx < BGRAPHS * HDIM) { g_hl[idx] = 0.f; g_cl[idx] = 0.f; g_r[idx] = 0.f; }
}

__global__ void __launch_bounds__(256) k_lstm(const float* __restrict__ Wih,
                                              const float* __restrict__ Whh,
                                              const float* __restrict__ bih,
                                              const float* __restrict__ bhh) {
    int b = blockIdx.x;
    int tid = threadIdx.x;              // 256
    __shared__ float qs[128];           // [hl | r] = prev q_star
    __shared__ float gates[256];
    if (tid < 64)  qs[tid] = g_hl[b * HDIM + tid];
    else if (tid < 128) qs[tid] = g_r[b * HDIM + (tid - 64)];
    __syncthreads();
    float acc = bih[tid] + bhh[tid];
#pragma unroll 16
    for (int j = 0; j < 128; j++) acc = fmaf(qs[j], Wih[tid * 128 + j], acc);
#pragma unroll 16
    for (int j = 0; j < 64; j++)  acc = fmaf(qs[j], Whh[tid * 64 + j], acc);
    gates[tid] = acc;
    __syncthreads();
    if (tid < 64) {
        float ig = gates[tid];
        float fg = gates[64 + tid];
        float gg = gates[128 + tid];
        float og = gates[192 + tid];
        float c = sigf(fg) * g_cl[b * HDIM + tid] + sigf(ig) * tanhf(gg);
        float hn = sigf(og) * tanhf(c);
        g_cl[b * HDIM + tid] = c;
        g_hl[b * HDIM + tid] = hn;
    }
}

__global__ void k_attn_init() {
    int idx = blockIdx.x * 256 + threadIdx.x;
    if (idx < BGRAPHS * HDIM) g_r[idx] = 0.f;
    if (idx < BGRAPHS) { g_mkey[idx] = (int)0x80000000; g_sden[idx] = 0.f; }
}

__global__ void k_attn_e(const int* __restrict__ batch) {
    int w = (blockIdx.x * 256 + threadIdx.x) >> 5;
    int lane = threadIdx.x & 31;
    if (w >= NODES) return;
    int b = batch[w];
    float v = g_h[w * HDIM + lane]      * g_hl[b * HDIM + lane]
            + g_h[w * HDIM + 32 + lane] * g_hl[b * HDIM + 32 + lane];
#pragma unroll
    for (int off = 16; off; off >>= 1) v += __shfl_xor_sync(0xffffffffu, v, off);
    if (lane == 0) {
        g_e[w] = v;
        atomicMax(&g_mkey[b], fkey(v));
    }
}

__global__ void k_attn_ex(const int* __restrict__ batch) {
    int n = blockIdx.x * 256 + threadIdx.x;
    if (n >= NODES) return;
    int b = batch[n];
    float m = funkey(g_mkey[b]);
    float ex = expf(g_e[n] - m);
    g_ex[n] = ex;
    atomicAdd(&g_sden[b], ex);
}

__global__ void k_attn_r(const int* __restrict__ batch) {
    int w = (blockIdx.x * 256 + threadIdx.x) >> 5;
    int lane = threadIdx.x & 31;
    if (w >= NODES) return;
    int b = batch[w];
    float a = g_ex[w] / g_sden[b];
    atomicAdd(&g_r[b * HDIM + lane],      a * g_h[w * HDIM + lane]);
    atomicAdd(&g_r[b * HDIM + 32 + lane], a * g_h[w * HDIM + 32 + lane]);
}

// ---------------- regression head ----------------------------------------
__global__ void __launch_bounds__(64) k_head(const float* __restrict__ hW1,
                                             const float* __restrict__ hb1,
                                             const float* __restrict__ hW2,
                                             const float* __restrict__ hb2,
                                             const float* __restrict__ hW3,
                                             const float* __restrict__ hb3,
                                             float* __restrict__ out) {
    int b = blockIdx.x;
    int tid = threadIdx.x;              // 64
    __shared__ float qs[128];
    __shared__ float z1[64];
    __shared__ float z2[32];
    qs[tid]      = g_hl[b * HDIM + tid];
    qs[64 + tid] = g_r [b * HDIM + tid];
    __syncthreads();
    float s = hb1[tid];
#pragma unroll 16
    for (int i = 0; i < 128; i++) s = fmaf(qs[i], hW1[i * 64 + tid], s);
    z1[tid] = fmaxf(s, 0.f);
    __syncthreads();
    if (tid < 32) {
        float t = hb2[tid];
#pragma unroll 16
        for (int i = 0; i < 64; i++) t = fmaf(z1[i], hW2[i * 32 + tid], t);
        z2[tid] = fmaxf(t, 0.f);
    }
    __syncthreads();
    if (tid == 0) {
        float o = hb3[0];
        for (int i = 0; i < 32; i++) o = fmaf(z2[i], hW3[i], o);
        out[b] = o;
    }
}

// ---------------- launch ---------------------------------------------------
extern "C" void kernel_launch(void* const* d_in, const int* in_sizes, int n_in,
                              void* d_out, int out_size) {
    const float* x      = (const float*)d_in[0];
    const int*   ei     = (const int*)  d_in[1];
    const float* ea     = (const float*)d_in[2];
    const int*   batch  = (const int*)  d_in[3];
    const float* W_enc  = (const float*)d_in[4];
    const float* b_enc  = (const float*)d_in[5];
    const float* eW1    = (const float*)d_in[6];
    const float* eb1    = (const float*)d_in[7];
    const float* eW2    = (const float*)d_in[8];
    const float* eb2    = (const float*)d_in[9];
    const float* root   = (const float*)d_in[10];
    const float* cbias  = (const float*)d_in[11];
    const float* gamma_ = (const float*)d_in[12];
    const float* beta_  = (const float*)d_in[13];
    const float* Wih    = (const float*)d_in[14];
    const float* Whh    = (const float*)d_in[15];
    const float* bih    = (const float*)d_in[16];
    const float* bhh    = (const float*)d_in[17];
    const float* hW1    = (const float*)d_in[18];
    const float* hb1    = (const float*)d_in[19];
    const float* hW2    = (const float*)d_in[20];
    const float* hb2    = (const float*)d_in[21];
    const float* hW3    = (const float*)d_in[22];
    const float* hb3    = (const float*)d_in[23];
    float* out = (float*)d_out;

    const int* src = ei;            // edge_index[0]
    const int* dst = ei + EDGES;    // edge_index[1]

    k_encoder<<<NODES, 64>>>(x, W_enc, b_enc);
    k_degcount<<<(EDGES + 255) / 256, 256>>>(dst);

    for (int l = 0; l < LAYERS; l++) {
        k_edge_mlp<<<(EDGES + 63) / 64, 256>>>(ea, eW1 + l * EDGE_D * HDIM, eb1 + l * HDIM);
        k_zero<<<(NODES * HDIM + 255) / 256, 256>>>();
        dim3 mg((EDGES + 63) / 64, KSPLITS);
        k_msg<<<mg, 128>>>(eW2 + l * HDIM * HDIM * HDIM, eb2 + l * HDIM * HDIM, src, dst);
        k_update<<<(NODES + 15) / 16, 256>>>(root + l * HDIM * HDIM, cbias + l * HDIM);
        k_bn_apply<<<(NODES * HDIM + 255) / 256, 256>>>(gamma_ + l * HDIM, beta_ + l * HDIM);
    }

    k_s2s_init<<<(BGRAPHS * HDIM + 255) / 256, 256>>>();
    for (int s = 0; s < STEPS; s++) {
        k_lstm<<<BGRAPHS, 256>>>(Wih, Whh, bih, bhh);
        k_attn_init<<<(BGRAPHS * HDIM + 255) / 256, 256>>>();
        k_attn_e<<<(NODES * 32 + 255) / 256, 256>>>(batch);
        k_attn_ex<<<(NODES + 255) / 256, 256>>>(batch);
        k_attn_r<<<(NODES * 32 + 255) / 256, 256>>>(batch);
    }
    k_head<<<BGRAPHS, 64>>>(hW1, hb1, hW2, hb2, hW3, hb3, out);
}